// round 15
// baseline (speedup 1.0000x reference)
#include <cuda_runtime.h>

#define NN 50000
#define NE 640000
#define H 128
#define NL 4
#define NRBF 50
#define NG 64
#define LN_EPS 1e-5f
#define RBF_STEP (4.0f / 49.0f)
#define RBF_COEFF (-75.03125f)   // -0.5 / (4/49)^2

#define T_TAB 2048
#define TAB_STEP (4.0f / (T_TAB - 1))
#define TAB_INV ((float)(T_TAB - 1) / 4.0f)

// ---------------- f32x2 helpers ----------------
union F2U { float2 f; unsigned long long u; };

__device__ __forceinline__ unsigned long long ffma2(unsigned long long a,
                                                    unsigned long long b,
                                                    unsigned long long c) {
    unsigned long long d;
    asm("fma.rn.f32x2 %0, %1, %2, %3;" : "=l"(d) : "l"(a), "l"(b), "l"(c));
    return d;
}
__device__ __forceinline__ unsigned long long dup2(float v) {
    unsigned long long d;
    asm("mov.b64 %0, {%1, %1};" : "=l"(d) : "f"(v));
    return d;
}

// ---------------- device scratch ----------------
__device__ float g_h[NN * H];
__device__ float g_xl[NN * H];
__device__ float g_tab[NL * T_TAB * H];   // all 4 filter tables (4 MB)
__device__ float g_pool[NG * H];
__device__ float g_cnt[NG];
// edge CSR (sorted by destination row)
__device__ int   g_hist[NN];   // zero at load; re-zeroed by k_scan after use
__device__ int   g_off[NN];    // after k_scatter: inclusive prefix = row end offsets
__device__ int2  g_sp[NE];     // sorted {f_bits, col}

// ---------------- init: h = emb[x]; pool/cnt = 0; hist accumulate ----------------
// g_hist is zero on entry (module load, or re-zeroed by previous k_scan).
__global__ void k_init(const int* __restrict__ x, const float* __restrict__ emb,
                       const int* __restrict__ erow) {
    int gid = blockIdx.x * blockDim.x + threadIdx.x;
    int node = gid >> 5, lane = gid & 31;
    if (node < NN) {
        int xi = x[node];
        float4 v = ((const float4*)(emb + (size_t)xi * H))[lane];
        ((float4*)(g_h + (size_t)node * H))[lane] = v;
    }
    if (gid < NG * H) g_pool[gid] = 0.f;
    if (gid < NG) g_cnt[gid] = 0.f;
    if (gid < NE) atomicAdd(&g_hist[__ldg(erow + gid)], 1);
}

// ---------------- exclusive scan over NN bins (1 block, 1024 threads); re-zero hist ----------------
__global__ void k_scan() {
    __shared__ int part[1024];
    const int PER = (NN + 1023) / 1024;   // 49
    int tid = threadIdx.x;
    int base = tid * PER;
    int s = 0;
    for (int j = 0; j < PER; j++) {
        int b = base + j;
        if (b < NN) s += g_hist[b];
    }
    part[tid] = s;
    __syncthreads();
    for (int d = 1; d < 1024; d <<= 1) {
        int v = (tid >= d) ? part[tid - d] : 0;
        __syncthreads();
        part[tid] += v;
        __syncthreads();
    }
    int run = part[tid] - s;
    for (int j = 0; j < PER; j++) {
        int b = base + j;
        if (b < NN) {
            g_off[b] = run;
            run += g_hist[b];
            g_hist[b] = 0;      // leave hist zeroed for the next invocation
        }
    }
}

// ---------------- scatter edges into row-sorted CSR order ----------------
__global__ void k_scatter(const float* __restrict__ eattr,
                          const int* __restrict__ erow, const int* __restrict__ ecol) {
    int e = blockIdx.x * blockDim.x + threadIdx.x;
    if (e >= NE) return;
    int rn = __ldg(erow + e);
    float f = __ldg(eattr + e) * TAB_INV;
    int pos = atomicAdd(&g_off[rn], 1);
    g_sp[pos] = make_int2(__float_as_int(f), __ldg(ecol + e));
}

// ---------------- xl = h @ lw + lb  (8 nodes per warp, f32x2 node-pair packed) ----------------
__global__ __launch_bounds__(256) void k_xl(const float* __restrict__ lw,
                                            const float* __restrict__ lb) {
    extern __shared__ float s[];
    float* lws = s;                 // H*H
    float* lbs = s + H * H;         // H
    float2* hs = (float2*)(s + H * H + H);  // 8 warps * 4 pairs * H float2 (32 KB)

    int tid = threadIdx.x;
    for (int i = tid; i < H * H / 4; i += blockDim.x)
        ((float4*)lws)[i] = ((const float4*)lw)[i];
    if (tid < H) lbs[tid] = lb[tid];
    __syncthreads();

    int warp = tid >> 5, lane = tid & 31;
    float2* hs_w = hs + warp * 4 * H;
    int wpb = blockDim.x >> 5;
    int nwarps = wpb * gridDim.x;
    int gw = blockIdx.x * wpb + warp;

    unsigned long long bia[4];
    #pragma unroll
    for (int g = 0; g < 4; g++) bia[g] = dup2(lbs[lane + 32 * g]);

    for (int n0 = gw * 8; n0 < NN; n0 += nwarps * 8) {   // NN % 8 == 0
        #pragma unroll
        for (int q = 0; q < 4; q++) {
            int nA = n0 + 2 * q, nB = nA + 1;
            const float* ha = g_h + (size_t)nA * H;
            const float* hb = g_h + (size_t)nB * H;
            #pragma unroll
            for (int g = 0; g < 4; g++) {
                int k = lane + 32 * g;
                hs_w[q * H + k] = make_float2(ha[k], hb[k]);
            }
        }
        __syncwarp();

        unsigned long long acc[4][4];
        #pragma unroll
        for (int q = 0; q < 4; q++)
            #pragma unroll
            for (int g = 0; g < 4; g++) acc[q][g] = bia[g];

        #pragma unroll 4
        for (int k = 0; k < H; k++) {
            const float* wr = lws + k * H;
            unsigned long long d0 = dup2(wr[lane]);
            unsigned long long d1 = dup2(wr[lane + 32]);
            unsigned long long d2 = dup2(wr[lane + 64]);
            unsigned long long d3 = dup2(wr[lane + 96]);
            #pragma unroll
            for (int q = 0; q < 4; q++) {
                F2U hv; hv.f = hs_w[q * H + k];      // broadcast LDS.64
                acc[q][0] = ffma2(hv.u, d0, acc[q][0]);
                acc[q][1] = ffma2(hv.u, d1, acc[q][1]);
                acc[q][2] = ffma2(hv.u, d2, acc[q][2]);
                acc[q][3] = ffma2(hv.u, d3, acc[q][3]);
            }
        }

        #pragma unroll
        for (int q = 0; q < 4; q++) {
            int nA = n0 + 2 * q, nB = nA + 1;
            float* oa = g_xl + (size_t)nA * H;
            float* ob = g_xl + (size_t)nB * H;
            #pragma unroll
            for (int g = 0; g < 4; g++) {
                F2U u; u.u = acc[q][g];
                oa[lane + 32 * g] = u.f.x;
                ob[lane + 32 * g] = u.f.y;
            }
        }
        __syncwarp();
    }
}

// ---------------- build ALL filter tables (blockIdx.y = layer) ----------------
__global__ __launch_bounds__(512, 1) void k_ftab4(
        const float* __restrict__ fw1b, const float* __restrict__ fb1b,
        const float* __restrict__ fw2b, const float* __restrict__ fb2b) {
    int layer = blockIdx.y;
    const float* fw1 = fw1b + (size_t)layer * NRBF * H;
    const float* fb1 = fb1b + (size_t)layer * H;
    const float* fw2 = fw2b + (size_t)layer * H * H;
    const float* fb2 = fb2b + (size_t)layer * H;
    float* tab = g_tab + (size_t)layer * T_TAB * H;

    extern __shared__ float s[];
    float* fw1s = s;                                 // 6400
    float* fw2s = fw1s + NRBF * H;                   // 16384
    float* fb1s = fw2s + H * H;                      // 128
    float* fb2s = fb1s + H;                          // 128
    float2* rbfp = (float2*)(fb2s + H);              // 16 warps * 2 pairs * NRBF
    float2* h1p  = rbfp + 16 * 2 * NRBF;             // 16 warps * 2 pairs * H

    int tid = threadIdx.x;
    for (int i = tid; i < NRBF * H / 4; i += blockDim.x)
        ((float4*)fw1s)[i] = ((const float4*)fw1)[i];
    for (int i = tid; i < H * H / 4; i += blockDim.x)
        ((float4*)fw2s)[i] = ((const float4*)fw2)[i];
    if (tid < H) { fb1s[tid] = fb1[tid]; fb2s[tid] = fb2[tid]; }
    __syncthreads();

    int warp = tid >> 5, lane = tid & 31;
    float2* my_rbf = rbfp + warp * 2 * NRBF;
    float2* my_h1  = h1p  + warp * 2 * H;
    int gw = blockIdx.x * (blockDim.x >> 5) + warp;
    int nwarps = gridDim.x * (blockDim.x >> 5);

    float2 b1a = ((const float2*)fb1s)[lane];
    float2 b1b = ((const float2*)(fb1s + 64))[lane];
    float2 b2a = ((const float2*)fb2s)[lane];
    float2 b2b = ((const float2*)(fb2s + 64))[lane];
    unsigned long long bi1[4] = { dup2(b1a.x), dup2(b1a.y), dup2(b1b.x), dup2(b1b.y) };
    unsigned long long bi2[4] = { dup2(b2a.x), dup2(b2a.y), dup2(b2b.x), dup2(b2b.y) };

    for (int t0 = gw * 4; t0 < T_TAB; t0 += nwarps * 4) {   // T_TAB % 4 == 0
        #pragma unroll
        for (int p = 0; p < 2; p++) {
            float d0 = (float)(t0 + 2 * p)     * TAB_STEP;
            float d1 = (float)(t0 + 2 * p + 1) * TAB_STEP;
            if (lane < NRBF) {
                float o = (float)lane * RBF_STEP;
                float u0 = d0 - o, u1 = d1 - o;
                my_rbf[p * NRBF + lane] =
                    make_float2(__expf(RBF_COEFF * u0 * u0), __expf(RBF_COEFF * u1 * u1));
            }
            int r2 = lane + 32;
            if (r2 < NRBF) {
                float o = (float)r2 * RBF_STEP;
                float u0 = d0 - o, u1 = d1 - o;
                my_rbf[p * NRBF + r2] =
                    make_float2(__expf(RBF_COEFF * u0 * u0), __expf(RBF_COEFF * u1 * u1));
            }
        }
        __syncwarp();

        unsigned long long acc[2][4];
        #pragma unroll
        for (int p = 0; p < 2; p++)
            #pragma unroll
            for (int g = 0; g < 4; g++) acc[p][g] = bi1[g];

        #pragma unroll 2
        for (int r = 0; r < NRBF; r++) {
            float2 wa = ((const float2*)(fw1s + r * H))[lane];
            float2 wb = ((const float2*)(fw1s + r * H + 64))[lane];
            unsigned long long d0 = dup2(wa.x), d1 = dup2(wa.y);
            unsigned long long d2 = dup2(wb.x), d3 = dup2(wb.y);
            #pragma unroll
            for (int p = 0; p < 2; p++) {
                F2U rb; rb.f = my_rbf[p * NRBF + r];
                acc[p][0] = ffma2(rb.u, d0, acc[p][0]);
                acc[p][1] = ffma2(rb.u, d1, acc[p][1]);
                acc[p][2] = ffma2(rb.u, d2, acc[p][2]);
                acc[p][3] = ffma2(rb.u, d3, acc[p][3]);
            }
        }
        #pragma unroll
        for (int p = 0; p < 2; p++) {
            F2U u0, u1, u2, u3;
            u0.u = acc[p][0]; u1.u = acc[p][1]; u2.u = acc[p][2]; u3.u = acc[p][3];
            u0.f.x = fmaxf(u0.f.x, 0.f); u0.f.y = fmaxf(u0.f.y, 0.f);
            u1.f.x = fmaxf(u1.f.x, 0.f); u1.f.y = fmaxf(u1.f.y, 0.f);
            u2.f.x = fmaxf(u2.f.x, 0.f); u2.f.y = fmaxf(u2.f.y, 0.f);
            u3.f.x = fmaxf(u3.f.x, 0.f); u3.f.y = fmaxf(u3.f.y, 0.f);
            my_h1[p * H + 2 * lane]      = u0.f;
            my_h1[p * H + 2 * lane + 1]  = u1.f;
            my_h1[p * H + 64 + 2 * lane] = u2.f;
            my_h1[p * H + 65 + 2 * lane] = u3.f;
        }
        __syncwarp();

        #pragma unroll
        for (int p = 0; p < 2; p++)
            #pragma unroll
            for (int g = 0; g < 4; g++) acc[p][g] = bi2[g];

        #pragma unroll 4
        for (int j = 0; j < H; j++) {
            float2 wa = ((const float2*)(fw2s + j * H))[lane];
            float2 wb = ((const float2*)(fw2s + j * H + 64))[lane];
            unsigned long long d0 = dup2(wa.x), d1 = dup2(wa.y);
            unsigned long long d2 = dup2(wb.x), d3 = dup2(wb.y);
            #pragma unroll
            for (int p = 0; p < 2; p++) {
                F2U hv; hv.f = my_h1[p * H + j];
                acc[p][0] = ffma2(hv.u, d0, acc[p][0]);
                acc[p][1] = ffma2(hv.u, d1, acc[p][1]);
                acc[p][2] = ffma2(hv.u, d2, acc[p][2]);
                acc[p][3] = ffma2(hv.u, d3, acc[p][3]);
            }
        }

        #pragma unroll
        for (int p = 0; p < 2; p++) {
            F2U a0, a1, a2, a3;
            a0.u = acc[p][0]; a1.u = acc[p][1]; a2.u = acc[p][2]; a3.u = acc[p][3];
            float* o0 = tab + (size_t)(t0 + 2 * p) * H;
            float* o1 = o0 + H;
            ((float2*)o0)[lane]        = make_float2(a0.f.x, a1.f.x);
            ((float2*)(o0 + 64))[lane] = make_float2(a2.f.x, a3.f.x);
            ((float2*)o1)[lane]        = make_float2(a0.f.y, a1.f.y);
            ((float2*)(o1 + 64))[lane] = make_float2(a2.f.y, a3.f.y);
        }
        __syncwarp();
    }
}

// ---------------- fused: CSR message gather + LayerNorm + (last layer) mean pool ----------------
__global__ __launch_bounds__(256) void k_msgln(int layer,
                                               const float* __restrict__ gam,
                                               const float* __restrict__ bet,
                                               const int* __restrict__ batch) {
    int tid = threadIdx.x;
    int warp = tid >> 5, lane = tid & 31;
    int gw = blockIdx.x * (blockDim.x >> 5) + warp;
    int nwarps = gridDim.x * (blockDim.x >> 5);
    // table base computed in device code (device-symbol arithmetic invalid on host)
    const float4* tab4 = (const float4*)(g_tab + (size_t)layer * T_TAB * H);
    const float4* xl4  = (const float4*)g_xl;

    float4 gm = ((const float4*)gam)[lane];
    float4 bt = ((const float4*)bet)[lane];

    for (int node = gw; node < NN; node += nwarps) {
        int start = (node == 0) ? 0 : g_off[node - 1];
        int end = g_off[node];
        float4 acc = make_float4(0.f, 0.f, 0.f, 0.f);

        for (int e0 = start; e0 < end; e0 += 4) {
            int m = end - e0; if (m > 4) m = 4;
            float4 w0[4], w1[4], xv[4];
            float tt[4];
            #pragma unroll
            for (int t = 0; t < 4; t++) {
                if (t < m) {
                    int2 p = g_sp[e0 + t];
                    float f = __int_as_float(p.x);
                    int i = (int)f;
                    if (i > T_TAB - 2) i = T_TAB - 2;
                    if (i < 0) i = 0;
                    tt[t] = f - (float)i;
                    w0[t] = tab4[(size_t)i * 32 + lane];
                    w1[t] = tab4[(size_t)i * 32 + 32 + lane];
                    xv[t] = xl4[(size_t)p.y * 32 + lane];
                }
            }
            #pragma unroll
            for (int t = 0; t < 4; t++) {
                if (t < m) {
                    float u = tt[t];
                    acc.x += xv[t].x * fmaf(u, w1[t].x - w0[t].x, w0[t].x);
                    acc.y += xv[t].y * fmaf(u, w1[t].y - w0[t].y, w0[t].y);
                    acc.z += xv[t].z * fmaf(u, w1[t].z - w0[t].z, w0[t].z);
                    acc.w += xv[t].w * fmaf(u, w1[t].w - w0[t].w, w0[t].w);
                }
            }
        }

        // ---- LayerNorm(h + acc) in-register (exclusive node owner) ----
        float4 hv = ((const float4*)(g_h + (size_t)node * H))[lane];
        float v0 = hv.x + acc.x, v1 = hv.y + acc.y, v2 = hv.z + acc.z, v3 = hv.w + acc.w;
        float sum = v0 + v1 + v2 + v3;
        #pragma unroll
        for (int o = 16; o > 0; o >>= 1) sum += __shfl_xor_sync(0xffffffffu, sum, o);
        float mu = sum * (1.f / H);
        float d0 = v0 - mu, d1 = v1 - mu, d2 = v2 - mu, d3 = v3 - mu;
        float vs = d0 * d0 + d1 * d1 + d2 * d2 + d3 * d3;
        #pragma unroll
        for (int o = 16; o > 0; o >>= 1) vs += __shfl_xor_sync(0xffffffffu, vs, o);
        float rs = rsqrtf(vs * (1.f / H) + LN_EPS);
        float4 outv = make_float4(d0 * rs * gm.x + bt.x, d1 * rs * gm.y + bt.y,
                                  d2 * rs * gm.z + bt.z, d3 * rs * gm.w + bt.w);
        if (batch == nullptr) {
            ((float4*)(g_h + (size_t)node * H))[lane] = outv;
        } else {
            int bg = batch[node];
            float* pp = g_pool + bg * H + 4 * lane;
            atomicAdd(pp,     outv.x);
            atomicAdd(pp + 1, outv.y);
            atomicAdd(pp + 2, outv.z);
            atomicAdd(pp + 3, outv.w);
            if (lane == 0) atomicAdd(&g_cnt[bg], 1.f);
        }
    }
}

__global__ void k_div(float* __restrict__ out) {
    int i = blockIdx.x * blockDim.x + threadIdx.x;
    if (i < NG * H) out[i] = g_pool[i] / fmaxf(g_cnt[i / H], 1.f);
}

// ---------------- launch ----------------
extern "C" void kernel_launch(void* const* d_in, const int* in_sizes, int n_in,
                              void* d_out, int out_size) {
    const int*   x     = (const int*)d_in[0];
    const int*   ei    = (const int*)d_in[1];
    const float* ea    = (const float*)d_in[2];
    const int*   batch = (const int*)d_in[3];
    const float* emb   = (const float*)d_in[4];
    const float* fw1   = (const float*)d_in[5];
    const float* fb1   = (const float*)d_in[6];
    const float* fw2   = (const float*)d_in[7];
    const float* fb2   = (const float*)d_in[8];
    const float* lw    = (const float*)d_in[9];
    const float* lb    = (const float*)d_in[10];
    const float* lng   = (const float*)d_in[11];
    const float* lnb   = (const float*)d_in[12];
    float* out = (float*)d_out;

    const int XL_SMEM = (H * H + H) * sizeof(float) + 8 * 4 * H * sizeof(float2); // ~96.5 KB
    const int FT_SMEM = (NRBF * H + H * H + 2 * H) * sizeof(float)
                      + 16 * 2 * NRBF * sizeof(float2)
                      + 16 * 2 * H * sizeof(float2);                              // ~138 KB
    cudaFuncSetAttribute(k_xl,    cudaFuncAttributeMaxDynamicSharedMemorySize, XL_SMEM);
    cudaFuncSetAttribute(k_ftab4, cudaFuncAttributeMaxDynamicSharedMemorySize, FT_SMEM);

    int node_blocks = (NN * 32 + 255) / 256;
    int edge_blocks = (NE + 255) / 256;

    k_init<<<node_blocks, 256>>>(x, emb, ei);       // h init + pool/cnt zero + hist
    k_scan<<<1, 1024>>>();                          // prefix sum + hist re-zero
    k_scatter<<<edge_blocks, 256>>>(ea, ei, ei + NE);
    k_ftab4<<<dim3(148, NL), 512, FT_SMEM>>>(fw1, fb1, fw2, fb2);
    for (int i = 0; i < NL; i++) {
        k_xl<<<296, 256, XL_SMEM>>>(lw + (size_t)i * H * H, lb + (size_t)i * H);
        k_msgln<<<740, 256>>>(i, lng + (size_t)i * H, lnb + (size_t)i * H,
                              (i == NL - 1) ? batch : nullptr);
    }
    k_div<<<(NG * H + 255) / 256, 256>>>(out);
}

// round 16
// speedup vs baseline: 1.0697x; 1.0697x over previous
#include <cuda_runtime.h>

#define NN 50000
#define NE 640000
#define H 128
#define NL 4
#define NRBF 50
#define NG 64
#define LN_EPS 1e-5f
#define RBF_STEP (4.0f / 49.0f)
#define RBF_COEFF (-75.03125f)   // -0.5 / (4/49)^2

#define T_TAB 2048
#define TAB_STEP (4.0f / (T_TAB - 1))
#define TAB_INV ((float)(T_TAB - 1) / 4.0f)

// ---------------- f32x2 helpers ----------------
union F2U { float2 f; unsigned long long u; };

__device__ __forceinline__ unsigned long long ffma2(unsigned long long a,
                                                    unsigned long long b,
                                                    unsigned long long c) {
    unsigned long long d;
    asm("fma.rn.f32x2 %0, %1, %2, %3;" : "=l"(d) : "l"(a), "l"(b), "l"(c));
    return d;
}
__device__ __forceinline__ unsigned long long dup2(float v) {
    unsigned long long d;
    asm("mov.b64 %0, {%1, %1};" : "=l"(d) : "f"(v));
    return d;
}

// ---------------- device scratch ----------------
__device__ float g_h[NN * H];
__device__ float g_xl[NN * H];
__device__ float g_tab[NL * T_TAB * H];   // per-layer filter tables (4 MB)
__device__ float g_pool[NG * H];
__device__ float g_cnt[NG];
// edge CSR (sorted by destination row)
__device__ int   g_hist[NN];
__device__ int   g_off[NN];    // after k_scatter: inclusive prefix = row end offsets
__device__ int2  g_sp[NE];     // sorted {f_bits, col}

// ---------------- init: h = emb[x]; pool/cnt/hist = 0 ----------------
__global__ void k_init(const int* __restrict__ x, const float* __restrict__ emb) {
    int gid = blockIdx.x * blockDim.x + threadIdx.x;
    int node = gid >> 5, lane = gid & 31;
    if (node < NN) {
        int xi = x[node];
        float4 v = ((const float4*)(emb + (size_t)xi * H))[lane];
        ((float4*)(g_h + (size_t)node * H))[lane] = v;
    }
    if (gid < NG * H) g_pool[gid] = 0.f;
    if (gid < NG) g_cnt[gid] = 0.f;
    if (gid < NN) g_hist[gid] = 0;
}

// ---------------- edge histogram by destination row ----------------
__global__ void k_hist(const int* __restrict__ erow) {
    int e = blockIdx.x * blockDim.x + threadIdx.x;
    if (e >= NE) return;
    atomicAdd(&g_hist[__ldg(erow + e)], 1);
}

// ---------------- exclusive scan over NN bins (1 block, 1024 threads) ----------------
__global__ void k_scan() {
    __shared__ int part[1024];
    const int PER = (NN + 1023) / 1024;   // 49
    int tid = threadIdx.x;
    int base = tid * PER;
    int s = 0;
    for (int j = 0; j < PER; j++) {
        int b = base + j;
        if (b < NN) s += g_hist[b];
    }
    part[tid] = s;
    __syncthreads();
    for (int d = 1; d < 1024; d <<= 1) {
        int v = (tid >= d) ? part[tid - d] : 0;
        __syncthreads();
        part[tid] += v;
        __syncthreads();
    }
    int run = part[tid] - s;
    for (int j = 0; j < PER; j++) {
        int b = base + j;
        if (b < NN) {
            g_off[b] = run;
            run += g_hist[b];
        }
    }
}

// ---------------- scatter edges into row-sorted CSR order ----------------
__global__ void k_scatter(const float* __restrict__ eattr,
                          const int* __restrict__ erow, const int* __restrict__ ecol) {
    int e = blockIdx.x * blockDim.x + threadIdx.x;
    if (e >= NE) return;
    int rn = __ldg(erow + e);
    float f = __ldg(eattr + e) * TAB_INV;
    int pos = atomicAdd(&g_off[rn], 1);
    g_sp[pos] = make_int2(__float_as_int(f), __ldg(ecol + e));
}

// ---------------- xl = h @ lw + lb  (8 nodes per warp, f32x2 node-pair packed) ----------------
__global__ __launch_bounds__(256) void k_xl(const float* __restrict__ lw,
                                            const float* __restrict__ lb) {
    extern __shared__ float s[];
    float* lws = s;                 // H*H
    float* lbs = s + H * H;         // H
    float2* hs = (float2*)(s + H * H + H);  // 8 warps * 4 pairs * H float2 (32 KB)

    int tid = threadIdx.x;
    for (int i = tid; i < H * H / 4; i += blockDim.x)
        ((float4*)lws)[i] = ((const float4*)lw)[i];
    if (tid < H) lbs[tid] = lb[tid];
    __syncthreads();

    int warp = tid >> 5, lane = tid & 31;
    float2* hs_w = hs + warp * 4 * H;
    int wpb = blockDim.x >> 5;
    int nwarps = wpb * gridDim.x;
    int gw = blockIdx.x * wpb + warp;

    unsigned long long bia[4];
    #pragma unroll
    for (int g = 0; g < 4; g++) bia[g] = dup2(lbs[lane + 32 * g]);

    for (int n0 = gw * 8; n0 < NN; n0 += nwarps * 8) {   // NN % 8 == 0
        #pragma unroll
        for (int q = 0; q < 4; q++) {
            int nA = n0 + 2 * q, nB = nA + 1;
            const float* ha = g_h + (size_t)nA * H;
            const float* hb = g_h + (size_t)nB * H;
            #pragma unroll
            for (int g = 0; g < 4; g++) {
                int k = lane + 32 * g;
                hs_w[q * H + k] = make_float2(ha[k], hb[k]);
            }
        }
        __syncwarp();

        unsigned long long acc[4][4];
        #pragma unroll
        for (int q = 0; q < 4; q++)
            #pragma unroll
            for (int g = 0; g < 4; g++) acc[q][g] = bia[g];

        #pragma unroll 4
        for (int k = 0; k < H; k++) {
            const float* wr = lws + k * H;
            unsigned long long d0 = dup2(wr[lane]);
            unsigned long long d1 = dup2(wr[lane + 32]);
            unsigned long long d2 = dup2(wr[lane + 64]);
            unsigned long long d3 = dup2(wr[lane + 96]);
            #pragma unroll
            for (int q = 0; q < 4; q++) {
                F2U hv; hv.f = hs_w[q * H + k];      // broadcast LDS.64
                acc[q][0] = ffma2(hv.u, d0, acc[q][0]);
                acc[q][1] = ffma2(hv.u, d1, acc[q][1]);
                acc[q][2] = ffma2(hv.u, d2, acc[q][2]);
                acc[q][3] = ffma2(hv.u, d3, acc[q][3]);
            }
        }

        #pragma unroll
        for (int q = 0; q < 4; q++) {
            int nA = n0 + 2 * q, nB = nA + 1;
            float* oa = g_xl + (size_t)nA * H;
            float* ob = g_xl + (size_t)nB * H;
            #pragma unroll
            for (int g = 0; g < 4; g++) {
                F2U u; u.u = acc[q][g];
                oa[lane + 32 * g] = u.f.x;
                ob[lane + 32 * g] = u.f.y;
            }
        }
        __syncwarp();
    }
}

// ---------------- build filter table for ONE layer (slice resolved in device code) ----------------
__global__ __launch_bounds__(512, 1) void k_ftab(
        int layer,
        const float* __restrict__ fw1, const float* __restrict__ fb1,
        const float* __restrict__ fw2, const float* __restrict__ fb2) {
    float* tab = g_tab + (size_t)layer * T_TAB * H;

    extern __shared__ float s[];
    float* fw1s = s;                                 // 6400
    float* fw2s = fw1s + NRBF * H;                   // 16384
    float* fb1s = fw2s + H * H;                      // 128
    float* fb2s = fb1s + H;                          // 128
    float2* rbfp = (float2*)(fb2s + H);              // 16 warps * 2 pairs * NRBF
    float2* h1p  = rbfp + 16 * 2 * NRBF;             // 16 warps * 2 pairs * H

    int tid = threadIdx.x;
    for (int i = tid; i < NRBF * H / 4; i += blockDim.x)
        ((float4*)fw1s)[i] = ((const float4*)fw1)[i];
    for (int i = tid; i < H * H / 4; i += blockDim.x)
        ((float4*)fw2s)[i] = ((const float4*)fw2)[i];
    if (tid < H) { fb1s[tid] = fb1[tid]; fb2s[tid] = fb2[tid]; }
    __syncthreads();

    int warp = tid >> 5, lane = tid & 31;
    float2* my_rbf = rbfp + warp * 2 * NRBF;
    float2* my_h1  = h1p  + warp * 2 * H;
    int gw = blockIdx.x * (blockDim.x >> 5) + warp;
    int nwarps = gridDim.x * (blockDim.x >> 5);

    float2 b1a = ((const float2*)fb1s)[lane];
    float2 b1b = ((const float2*)(fb1s + 64))[lane];
    float2 b2a = ((const float2*)fb2s)[lane];
    float2 b2b = ((const float2*)(fb2s + 64))[lane];
    unsigned long long bi1[4] = { dup2(b1a.x), dup2(b1a.y), dup2(b1b.x), dup2(b1b.y) };
    unsigned long long bi2[4] = { dup2(b2a.x), dup2(b2a.y), dup2(b2b.x), dup2(b2b.y) };

    for (int t0 = gw * 4; t0 < T_TAB; t0 += nwarps * 4) {   // T_TAB % 4 == 0
        #pragma unroll
        for (int p = 0; p < 2; p++) {
            float d0 = (float)(t0 + 2 * p)     * TAB_STEP;
            float d1 = (float)(t0 + 2 * p + 1) * TAB_STEP;
            if (lane < NRBF) {
                float o = (float)lane * RBF_STEP;
                float u0 = d0 - o, u1 = d1 - o;
                my_rbf[p * NRBF + lane] =
                    make_float2(__expf(RBF_COEFF * u0 * u0), __expf(RBF_COEFF * u1 * u1));
            }
            int r2 = lane + 32;
            if (r2 < NRBF) {
                float o = (float)r2 * RBF_STEP;
                float u0 = d0 - o, u1 = d1 - o;
                my_rbf[p * NRBF + r2] =
                    make_float2(__expf(RBF_COEFF * u0 * u0), __expf(RBF_COEFF * u1 * u1));
            }
        }
        __syncwarp();

        unsigned long long acc[2][4];
        #pragma unroll
        for (int p = 0; p < 2; p++)
            #pragma unroll
            for (int g = 0; g < 4; g++) acc[p][g] = bi1[g];

        #pragma unroll 2
        for (int r = 0; r < NRBF; r++) {
            float2 wa = ((const float2*)(fw1s + r * H))[lane];
            float2 wb = ((const float2*)(fw1s + r * H + 64))[lane];
            unsigned long long d0 = dup2(wa.x), d1 = dup2(wa.y);
            unsigned long long d2 = dup2(wb.x), d3 = dup2(wb.y);
            #pragma unroll
            for (int p = 0; p < 2; p++) {
                F2U rb; rb.f = my_rbf[p * NRBF + r];
                acc[p][0] = ffma2(rb.u, d0, acc[p][0]);
                acc[p][1] = ffma2(rb.u, d1, acc[p][1]);
                acc[p][2] = ffma2(rb.u, d2, acc[p][2]);
                acc[p][3] = ffma2(rb.u, d3, acc[p][3]);
            }
        }
        #pragma unroll
        for (int p = 0; p < 2; p++) {
            F2U u0, u1, u2, u3;
            u0.u = acc[p][0]; u1.u = acc[p][1]; u2.u = acc[p][2]; u3.u = acc[p][3];
            u0.f.x = fmaxf(u0.f.x, 0.f); u0.f.y = fmaxf(u0.f.y, 0.f);
            u1.f.x = fmaxf(u1.f.x, 0.f); u1.f.y = fmaxf(u1.f.y, 0.f);
            u2.f.x = fmaxf(u2.f.x, 0.f); u2.f.y = fmaxf(u2.f.y, 0.f);
            u3.f.x = fmaxf(u3.f.x, 0.f); u3.f.y = fmaxf(u3.f.y, 0.f);
            my_h1[p * H + 2 * lane]      = u0.f;
            my_h1[p * H + 2 * lane + 1]  = u1.f;
            my_h1[p * H + 64 + 2 * lane] = u2.f;
            my_h1[p * H + 65 + 2 * lane] = u3.f;
        }
        __syncwarp();

        #pragma unroll
        for (int p = 0; p < 2; p++)
            #pragma unroll
            for (int g = 0; g < 4; g++) acc[p][g] = bi2[g];

        #pragma unroll 4
        for (int j = 0; j < H; j++) {
            float2 wa = ((const float2*)(fw2s + j * H))[lane];
            float2 wb = ((const float2*)(fw2s + j * H + 64))[lane];
            unsigned long long d0 = dup2(wa.x), d1 = dup2(wa.y);
            unsigned long long d2 = dup2(wb.x), d3 = dup2(wb.y);
            #pragma unroll
            for (int p = 0; p < 2; p++) {
                F2U hv; hv.f = my_h1[p * H + j];
                acc[p][0] = ffma2(hv.u, d0, acc[p][0]);
                acc[p][1] = ffma2(hv.u, d1, acc[p][1]);
                acc[p][2] = ffma2(hv.u, d2, acc[p][2]);
                acc[p][3] = ffma2(hv.u, d3, acc[p][3]);
            }
        }

        #pragma unroll
        for (int p = 0; p < 2; p++) {
            F2U a0, a1, a2, a3;
            a0.u = acc[p][0]; a1.u = acc[p][1]; a2.u = acc[p][2]; a3.u = acc[p][3];
            float* o0 = tab + (size_t)(t0 + 2 * p) * H;
            float* o1 = o0 + H;
            ((float2*)o0)[lane]        = make_float2(a0.f.x, a1.f.x);
            ((float2*)(o0 + 64))[lane] = make_float2(a2.f.x, a3.f.x);
            ((float2*)o1)[lane]        = make_float2(a0.f.y, a1.f.y);
            ((float2*)(o1 + 64))[lane] = make_float2(a2.f.y, a3.f.y);
        }
        __syncwarp();
    }
}

// ---------------- fused: CSR message gather + LayerNorm + (last layer) mean pool ----------------
__global__ __launch_bounds__(256) void k_msgln(int layer,
                                               const float* __restrict__ gam,
                                               const float* __restrict__ bet,
                                               const int* __restrict__ batch) {
    int tid = threadIdx.x;
    int warp = tid >> 5, lane = tid & 31;
    int gw = blockIdx.x * (blockDim.x >> 5) + warp;
    int nwarps = gridDim.x * (blockDim.x >> 5);
    const float4* tab4 = (const float4*)(g_tab + (size_t)layer * T_TAB * H);
    const float4* xl4  = (const float4*)g_xl;

    float4 gm = ((const float4*)gam)[lane];
    float4 bt = ((const float4*)bet)[lane];

    for (int node = gw; node < NN; node += nwarps) {
        int start = (node == 0) ? 0 : g_off[node - 1];
        int end = g_off[node];
        float4 acc = make_float4(0.f, 0.f, 0.f, 0.f);

        for (int e0 = start; e0 < end; e0 += 4) {
            int m = end - e0; if (m > 4) m = 4;
            float4 w0[4], w1[4], xv[4];
            float tt[4];
            #pragma unroll
            for (int t = 0; t < 4; t++) {
                if (t < m) {
                    int2 p = g_sp[e0 + t];
                    float f = __int_as_float(p.x);
                    int i = (int)f;
                    if (i > T_TAB - 2) i = T_TAB - 2;
                    if (i < 0) i = 0;
                    tt[t] = f - (float)i;
                    w0[t] = tab4[(size_t)i * 32 + lane];
                    w1[t] = tab4[(size_t)i * 32 + 32 + lane];
                    xv[t] = xl4[(size_t)p.y * 32 + lane];
                }
            }
            #pragma unroll
            for (int t = 0; t < 4; t++) {
                if (t < m) {
                    float u = tt[t];
                    acc.x += xv[t].x * fmaf(u, w1[t].x - w0[t].x, w0[t].x);
                    acc.y += xv[t].y * fmaf(u, w1[t].y - w0[t].y, w0[t].y);
                    acc.z += xv[t].z * fmaf(u, w1[t].z - w0[t].z, w0[t].z);
                    acc.w += xv[t].w * fmaf(u, w1[t].w - w0[t].w, w0[t].w);
                }
            }
        }

        // ---- LayerNorm(h + acc) in-register (exclusive node owner) ----
        float4 hv = ((const float4*)(g_h + (size_t)node * H))[lane];
        float v0 = hv.x + acc.x, v1 = hv.y + acc.y, v2 = hv.z + acc.z, v3 = hv.w + acc.w;
        float sum = v0 + v1 + v2 + v3;
        #pragma unroll
        for (int o = 16; o > 0; o >>= 1) sum += __shfl_xor_sync(0xffffffffu, sum, o);
        float mu = sum * (1.f / H);
        float d0 = v0 - mu, d1 = v1 - mu, d2 = v2 - mu, d3 = v3 - mu;
        float vs = d0 * d0 + d1 * d1 + d2 * d2 + d3 * d3;
        #pragma unroll
        for (int o = 16; o > 0; o >>= 1) vs += __shfl_xor_sync(0xffffffffu, vs, o);
        float rs = rsqrtf(vs * (1.f / H) + LN_EPS);
        float4 outv = make_float4(d0 * rs * gm.x + bt.x, d1 * rs * gm.y + bt.y,
                                  d2 * rs * gm.z + bt.z, d3 * rs * gm.w + bt.w);
        if (batch == nullptr) {
            ((float4*)(g_h + (size_t)node * H))[lane] = outv;
        } else {
            int bg = batch[node];
            float* pp = g_pool + bg * H + 4 * lane;
            atomicAdd(pp,     outv.x);
            atomicAdd(pp + 1, outv.y);
            atomicAdd(pp + 2, outv.z);
            atomicAdd(pp + 3, outv.w);
            if (lane == 0) atomicAdd(&g_cnt[bg], 1.f);
        }
    }
}

__global__ void k_div(float* __restrict__ out) {
    int i = blockIdx.x * blockDim.x + threadIdx.x;
    if (i < NG * H) out[i] = g_pool[i] / fmaxf(g_cnt[i / H], 1.f);
}

// ---------------- launch ----------------
extern "C" void kernel_launch(void* const* d_in, const int* in_sizes, int n_in,
                              void* d_out, int out_size) {
    const int*   x     = (const int*)d_in[0];
    const int*   ei    = (const int*)d_in[1];
    const float* ea    = (const float*)d_in[2];
    const int*   batch = (const int*)d_in[3];
    const float* emb   = (const float*)d_in[4];
    const float* fw1   = (const float*)d_in[5];
    const float* fb1   = (const float*)d_in[6];
    const float* fw2   = (const float*)d_in[7];
    const float* fb2   = (const float*)d_in[8];
    const float* lw    = (const float*)d_in[9];
    const float* lb    = (const float*)d_in[10];
    const float* lng   = (const float*)d_in[11];
    const float* lnb   = (const float*)d_in[12];
    float* out = (float*)d_out;

    const int XL_SMEM = (H * H + H) * sizeof(float) + 8 * 4 * H * sizeof(float2); // ~96.5 KB
    const int FT_SMEM = (NRBF * H + H * H + 2 * H) * sizeof(float)
                      + 16 * 2 * NRBF * sizeof(float2)
                      + 16 * 2 * H * sizeof(float2);                              // ~138 KB
    cudaFuncSetAttribute(k_xl,   cudaFuncAttributeMaxDynamicSharedMemorySize, XL_SMEM);
    cudaFuncSetAttribute(k_ftab, cudaFuncAttributeMaxDynamicSharedMemorySize, FT_SMEM);

    int node_blocks = (NN * 32 + 255) / 256;
    int edge_blocks = (NE + 255) / 256;

    // Fork: build all filter tables on a side stream, concurrent with CSR prep.
    // (host-side resource creation only; few calls happen before graph replay)
    cudaStream_t s2;
    cudaEvent_t evFork, evJoin;
    cudaStreamCreateWithFlags(&s2, cudaStreamNonBlocking);
    cudaEventCreateWithFlags(&evFork, cudaEventDisableTiming);
    cudaEventCreateWithFlags(&evJoin, cudaEventDisableTiming);

    cudaEventRecord(evFork, 0);
    cudaStreamWaitEvent(s2, evFork, 0);
    for (int i = 0; i < NL; i++)
        k_ftab<<<148, 512, FT_SMEM, s2>>>(i,
                                          fw1 + (size_t)i * NRBF * H, fb1 + (size_t)i * H,
                                          fw2 + (size_t)i * H * H,    fb2 + (size_t)i * H);
    cudaEventRecord(evJoin, s2);

    // Main stream: prep chain
    k_init<<<node_blocks, 256>>>(x, emb);
    k_hist<<<edge_blocks, 256>>>(ei);
    k_scan<<<1, 1024>>>();
    k_scatter<<<edge_blocks, 256>>>(ea, ei, ei + NE);

    // Join: tables must be ready before first msgln
    cudaStreamWaitEvent(0, evJoin, 0);

    for (int i = 0; i < NL; i++) {
        k_xl<<<296, 256, XL_SMEM>>>(lw + (size_t)i * H * H, lb + (size_t)i * H);
        k_msgln<<<740, 256>>>(i, lng + (size_t)i * H, lnb + (size_t)i * H,
                              (i == NL - 1) ? batch : nullptr);
    }
    k_div<<<(NG * H + 255) / 256, 256>>>(out);
}